// round 6
// baseline (speedup 1.0000x reference)
#include <cuda_runtime.h>
#include <cuda_bf16.h>
#include <math.h>
#include <stdint.h>

#define HIDDEN 5120
#define NHEADS 16
#define QLORA  1536
#define KVLORA 512
#define NOPE   128
#define ROPE_D 64
#define QKD    192
#define VDIM   128
#define SEQ    2048
#define QKVN   2112
#define SM_SCALE 0.07216878364870322f  // 192^-0.5
#define RESID_SCALE 0.125f

// ---------------- scratch ----------------------------------------------------
static __device__ float g_qackv[SEQ * QKVN];
static __device__ float g_q[SEQ * NHEADS * QKD];
static __device__ float g_kv[SEQ * 4096];

static __device__ __nv_bfloat16 g_h_hi[SEQ * HIDDEN],    g_h_lo[SEQ * HIDDEN];
static __device__ __nv_bfloat16 g_qa_hi[SEQ * QLORA],    g_qa_lo[SEQ * QLORA];
static __device__ __nv_bfloat16 g_ckvn_hi[SEQ * KVLORA], g_ckvn_lo[SEQ * KVLORA];
static __device__ __nv_bfloat16 g_attn_hi[SEQ * 2048],   g_attn_lo[SEQ * 2048];
static __device__ __nv_bfloat16 g_qf_hi[NHEADS * SEQ * QKD], g_qf_lo[NHEADS * SEQ * QKD];
static __device__ __nv_bfloat16 g_k_hi[NHEADS * SEQ * QKD],  g_k_lo[NHEADS * SEQ * QKD];
static __device__ __nv_bfloat16 g_v_hi[NHEADS * SEQ * VDIM], g_v_lo[NHEADS * SEQ * VDIM];

static __device__ __nv_bfloat16 g_wqkva_hi[QKVN * HIDDEN], g_wqkva_lo[QKVN * HIDDEN];
static __device__ __nv_bfloat16 g_wqb_hi[3072 * QLORA],    g_wqb_lo[3072 * QLORA];
static __device__ __nv_bfloat16 g_wkvb_hi[4096 * KVLORA],  g_wkvb_lo[4096 * KVLORA];
static __device__ __nv_bfloat16 g_wo_hi[HIDDEN * 2048],    g_wo_lo[HIDDEN * 2048];

// ---------------- helpers ----------------------------------------------------
__device__ __forceinline__ uint32_t smem_u32(const void* p) {
    return (uint32_t)__cvta_generic_to_shared(p);
}
__device__ __forceinline__ void cpa16(uint32_t dst, const void* src, int sz) {
    asm volatile("cp.async.cg.shared.global [%0], [%1], 16, %2;"
                 :: "r"(dst), "l"(src), "r"(sz) : "memory");
}
#define CP_COMMIT() asm volatile("cp.async.commit_group;" ::: "memory")
#define CP_WAIT(n)  asm volatile("cp.async.wait_group %0;" :: "n"(n) : "memory")

__device__ __forceinline__ void ldsm4(uint32_t& r0, uint32_t& r1, uint32_t& r2, uint32_t& r3,
                                      uint32_t addr) {
    asm volatile("ldmatrix.sync.aligned.m8n8.x4.shared.b16 {%0,%1,%2,%3}, [%4];"
                 : "=r"(r0), "=r"(r1), "=r"(r2), "=r"(r3) : "r"(addr));
}
__device__ __forceinline__ void ldsm4t(uint32_t& r0, uint32_t& r1, uint32_t& r2, uint32_t& r3,
                                       uint32_t addr) {
    asm volatile("ldmatrix.sync.aligned.m8n8.x4.trans.shared.b16 {%0,%1,%2,%3}, [%4];"
                 : "=r"(r0), "=r"(r1), "=r"(r2), "=r"(r3) : "r"(addr));
}
__device__ __forceinline__ void mma16816(float* c, uint32_t a0, uint32_t a1, uint32_t a2,
                                         uint32_t a3, uint32_t b0, uint32_t b1) {
    asm volatile(
        "mma.sync.aligned.m16n8k16.row.col.f32.bf16.bf16.f32 "
        "{%0,%1,%2,%3}, {%4,%5,%6,%7}, {%8,%9}, {%0,%1,%2,%3};"
        : "+f"(c[0]), "+f"(c[1]), "+f"(c[2]), "+f"(c[3])
        : "r"(a0), "r"(a1), "r"(a2), "r"(a3), "r"(b0), "r"(b1));
}
__device__ __forceinline__ void split2(float v0, float v1, uint32_t& hi, uint32_t& lo) {
    __nv_bfloat16 h0 = __float2bfloat16(v0), h1 = __float2bfloat16(v1);
    float r0 = v0 - __bfloat162float(h0), r1 = v1 - __bfloat162float(h1);
    __nv_bfloat162 th; th.x = h0; th.y = h1;
    hi = *reinterpret_cast<uint32_t*>(&th);
    __nv_bfloat162 tl; tl.x = __float2bfloat16(r0); tl.y = __float2bfloat16(r1);
    lo = *reinterpret_cast<uint32_t*>(&tl);
}

// ---------------- vectorized fp32 -> bf16 hi/lo converters --------------------
__global__ void cvt_b16(const float* __restrict__ x, __nv_bfloat16* __restrict__ hi,
                        __nv_bfloat16* __restrict__ lo, long n)
{
    long n4 = n >> 2;
    const float4* x4 = (const float4*)x;
    __nv_bfloat162* h2 = (__nv_bfloat162*)hi;
    __nv_bfloat162* l2 = (__nv_bfloat162*)lo;
    for (long i = (long)blockIdx.x * blockDim.x + threadIdx.x; i < n4;
         i += (long)gridDim.x * blockDim.x) {
        float4 v = x4[i];
        __nv_bfloat162 ha; ha.x = __float2bfloat16(v.x); ha.y = __float2bfloat16(v.y);
        __nv_bfloat162 hb; hb.x = __float2bfloat16(v.z); hb.y = __float2bfloat16(v.w);
        __nv_bfloat162 la; la.x = __float2bfloat16(v.x - __bfloat162float(ha.x));
        la.y = __float2bfloat16(v.y - __bfloat162float(ha.y));
        __nv_bfloat162 lb; lb.x = __float2bfloat16(v.z - __bfloat162float(hb.x));
        lb.y = __float2bfloat16(v.w - __bfloat162float(hb.y));
        h2[2 * i] = ha; h2[2 * i + 1] = hb;
        l2[2 * i] = la; l2[2 * i + 1] = lb;
    }
}

__global__ void rmsnorm_b16(const float* __restrict__ x, const float* __restrict__ w,
                            __nv_bfloat16* __restrict__ hi, __nv_bfloat16* __restrict__ lo,
                            int cols, int strideIn, int strideOut)
{
    int row = blockIdx.x;
    int t = threadIdx.x;
    const float4* xr = (const float4*)(x + (long)row * strideIn);
    const float4* w4 = (const float4*)w;
    int c4 = cols >> 2;
    float ss = 0.f;
    for (int c = t; c < c4; c += 256) {
        float4 v = xr[c];
        ss = fmaf(v.x, v.x, fmaf(v.y, v.y, fmaf(v.z, v.z, fmaf(v.w, v.w, ss))));
    }
    __shared__ float red[256];
    red[t] = ss; __syncthreads();
    for (int s = 128; s > 0; s >>= 1) { if (t < s) red[t] += red[t + s]; __syncthreads(); }
    float scale = rsqrtf(red[0] / (float)cols + 1e-6f);
    __nv_bfloat162* hr = (__nv_bfloat162*)(hi + (long)row * strideOut);
    __nv_bfloat162* lr = (__nv_bfloat162*)(lo + (long)row * strideOut);
    for (int c = t; c < c4; c += 256) {
        float4 v = xr[c];
        float4 wv = w4[c];
        float a = v.x * scale * wv.x, b = v.y * scale * wv.y;
        float d = v.z * scale * wv.z, e = v.w * scale * wv.w;
        __nv_bfloat162 ha; ha.x = __float2bfloat16(a); ha.y = __float2bfloat16(b);
        __nv_bfloat162 hb; hb.x = __float2bfloat16(d); hb.y = __float2bfloat16(e);
        __nv_bfloat162 la; la.x = __float2bfloat16(a - __bfloat162float(ha.x));
        la.y = __float2bfloat16(b - __bfloat162float(ha.y));
        __nv_bfloat162 lb; lb.x = __float2bfloat16(d - __bfloat162float(hb.x));
        lb.y = __float2bfloat16(e - __bfloat162float(hb.y));
        hr[2 * c] = ha; hr[2 * c + 1] = hb;
        lr[2 * c] = la; lr[2 * c + 1] = lb;
    }
}

// ---------------- mma.sync bf16x3 GEMM core (2 stages, 2 CTAs/SM) -------------
#define GPADB 80
#define GT_BYTES (128 * GPADB)      // 10240
#define GS_BYTES (4 * GT_BYTES)     // 40960 per stage
#define GEMM_SMEM (2 * GS_BYTES)    // 81920

__device__ __forceinline__ void g_fill(uint32_t dstBase, const __nv_bfloat16* __restrict__ src,
                                       long ld, int rmax, int t)
{
#pragma unroll
    for (int i = 0; i < 2; ++i) {
        int id = t + 256 * i;
        int row = id >> 2, ch = id & 3;
        bool ok = row < rmax;
        const __nv_bfloat16* g = src + (long)(ok ? row : 0) * ld + ch * 8;
        cpa16(dstBase + row * GPADB + ch * 16, g, ok ? 16 : 0);
    }
}

__device__ __forceinline__ void gemm_core(
    const __nv_bfloat16* __restrict__ Ah, const __nv_bfloat16* __restrict__ Al, int lda,
    const __nv_bfloat16* __restrict__ Bh, const __nv_bfloat16* __restrict__ Bl,
    float* __restrict__ C, int M, int N, int K,
    const float* __restrict__ D, float beta, int bx, int by, char* smem)
{
    uint32_t sb = smem_u32(smem);
    int t = threadIdx.x;
    int warp = t >> 5, lane = t & 31;
    int wm = warp >> 2, wn = warp & 3;
    int n0 = bx * 128, m0 = by * 128;
    int nc = K / 32;

    float acc[4][4][4];
#pragma unroll
    for (int i = 0; i < 4; i++)
#pragma unroll
        for (int j = 0; j < 4; j++)
#pragma unroll
            for (int r = 0; r < 4; r++) acc[i][j][r] = 0.f;

    {
        g_fill(sb + 0 * GT_BYTES, Ah + (long)m0 * lda, lda, M - m0, t);
        g_fill(sb + 1 * GT_BYTES, Al + (long)m0 * lda, lda, M - m0, t);
        g_fill(sb + 2 * GT_BYTES, Bh + (long)n0 * K, K, N - n0, t);
        g_fill(sb + 3 * GT_BYTES, Bl + (long)n0 * K, K, N - n0, t);
        CP_COMMIT();
    }

    uint32_t aoff = (uint32_t)((wm * 64 + (lane & 15)) * GPADB + (lane >> 4) * 16);
    uint32_t boff = (uint32_t)(2 * GT_BYTES +
                               (wn * 32 + (lane & 7) + ((lane >> 4) << 3)) * GPADB +
                               ((lane >> 3) & 1) * 16);

    for (int c = 0; c < nc; ++c) {
        CP_WAIT(0);
        __syncthreads();
        if (c + 1 < nc) {
            uint32_t bn = sb + ((c + 1) & 1) * GS_BYTES;
            int kc0 = (c + 1) * 32;
            g_fill(bn + 0 * GT_BYTES, Ah + (long)m0 * lda + kc0, lda, M - m0, t);
            g_fill(bn + 1 * GT_BYTES, Al + (long)m0 * lda + kc0, lda, M - m0, t);
            g_fill(bn + 2 * GT_BYTES, Bh + (long)n0 * K + kc0, K, N - n0, t);
            g_fill(bn + 3 * GT_BYTES, Bl + (long)n0 * K + kc0, K, N - n0, t);
        }
        CP_COMMIT();

        uint32_t base = sb + (c & 1) * GS_BYTES;
#pragma unroll
        for (int k16 = 0; k16 < 2; ++k16) {
            uint32_t ah[4][4], al_[4][4];
#pragma unroll
            for (int im = 0; im < 4; ++im) {
                uint32_t addr = base + aoff + im * 16 * GPADB + k16 * 32;
                ldsm4(ah[im][0], ah[im][1], ah[im][2], ah[im][3], addr);
                ldsm4(al_[im][0], al_[im][1], al_[im][2], al_[im][3], addr + GT_BYTES);
            }
            uint32_t bh[4][2], bl[4][2];
#pragma unroll
            for (int j2 = 0; j2 < 2; ++j2) {
                uint32_t addr = base + boff + j2 * 16 * GPADB + k16 * 32;
                uint32_t r0, r1, r2, r3;
                ldsm4(r0, r1, r2, r3, addr);
                bh[2 * j2][0] = r0; bh[2 * j2][1] = r1;
                bh[2 * j2 + 1][0] = r2; bh[2 * j2 + 1][1] = r3;
                ldsm4(r0, r1, r2, r3, addr + GT_BYTES);
                bl[2 * j2][0] = r0; bl[2 * j2][1] = r1;
                bl[2 * j2 + 1][0] = r2; bl[2 * j2 + 1][1] = r3;
            }
#pragma unroll
            for (int im = 0; im < 4; ++im)
#pragma unroll
                for (int jn = 0; jn < 4; ++jn) {
                    mma16816(acc[im][jn], ah[im][0], ah[im][1], ah[im][2], ah[im][3],
                             bh[jn][0], bh[jn][1]);
                    mma16816(acc[im][jn], ah[im][0], ah[im][1], ah[im][2], ah[im][3],
                             bl[jn][0], bl[jn][1]);
                    mma16816(acc[im][jn], al_[im][0], al_[im][1], al_[im][2], al_[im][3],
                             bh[jn][0], bh[jn][1]);
                }
        }
    }

#pragma unroll
    for (int im = 0; im < 4; ++im) {
        int row0 = m0 + wm * 64 + im * 16 + (lane >> 2);
#pragma unroll
        for (int jn = 0; jn < 4; ++jn) {
            int col = n0 + wn * 32 + jn * 8 + (lane & 3) * 2;
            if (col < N) {
                float2 v0 = make_float2(acc[im][jn][0], acc[im][jn][1]);
                float2 v1 = make_float2(acc[im][jn][2], acc[im][jn][3]);
                if (D) {
                    float2 d0 = *(const float2*)&D[(long)row0 * N + col];
                    float2 d1 = *(const float2*)&D[(long)(row0 + 8) * N + col];
                    v0.x = fmaf(beta, d0.x, v0.x); v0.y = fmaf(beta, d0.y, v0.y);
                    v1.x = fmaf(beta, d1.x, v1.x); v1.y = fmaf(beta, d1.y, v1.y);
                }
                *(float2*)&C[(long)row0 * N + col] = v0;
                *(float2*)&C[(long)(row0 + 8) * N + col] = v1;
            }
        }
    }
}

__global__ __launch_bounds__(256, 2)
void gemm_mma(const __nv_bfloat16* __restrict__ Ah, const __nv_bfloat16* __restrict__ Al, int lda,
              const __nv_bfloat16* __restrict__ Bh, const __nv_bfloat16* __restrict__ Bl,
              float* __restrict__ C, int M, int N, int K,
              const float* __restrict__ D, float beta)
{
    extern __shared__ __align__(128) char smem[];
    gemm_core(Ah, Al, lda, Bh, Bl, C, M, N, K, D, beta, blockIdx.x, blockIdx.y, smem);
}

// two independent GEMMs in one launch (long-K job first for LPT backfill)
__global__ __launch_bounds__(256, 2)
void gemm_dual(const __nv_bfloat16* __restrict__ A1h, const __nv_bfloat16* __restrict__ A1l,
               int lda1, const __nv_bfloat16* __restrict__ B1h,
               const __nv_bfloat16* __restrict__ B1l, float* __restrict__ C1, int N1, int K1,
               const __nv_bfloat16* __restrict__ A2h, const __nv_bfloat16* __restrict__ A2l,
               int lda2, const __nv_bfloat16* __restrict__ B2h,
               const __nv_bfloat16* __restrict__ B2l, float* __restrict__ C2, int N2, int K2,
               int split)
{
    extern __shared__ __align__(128) char smem[];
    if ((int)blockIdx.x < split)
        gemm_core(A1h, A1l, lda1, B1h, B1l, C1, SEQ, N1, K1, nullptr, 0.f,
                  blockIdx.x, blockIdx.y, smem);
    else
        gemm_core(A2h, A2l, lda2, B2h, B2l, C2, SEQ, N2, K2, nullptr, 0.f,
                  blockIdx.x - split, blockIdx.y, smem);
}

// ---------------- RoPE + scatter ----------------------------------------------
__global__ void rope_scatter(const float* __restrict__ qin,    // [s][3072]
                             const float* __restrict__ qackv,  // [s][2112]
                             const float* __restrict__ kvin,   // [s][4096]
                             const int* __restrict__ pos_ids,
                             __nv_bfloat16* __restrict__ qh, __nv_bfloat16* __restrict__ ql,
                             float* __restrict__ kout,
                             __nv_bfloat16* __restrict__ kh, __nv_bfloat16* __restrict__ kl,
                             float* __restrict__ vout,
                             __nv_bfloat16* __restrict__ vh, __nv_bfloat16* __restrict__ vl)
{
    int s = blockIdx.x;
    int t = threadIdx.x;
    __shared__ float cs[32], sn[32], kr[64];
    if (t < 32) {
        double invf = exp(-(double)t * 0.28782313662425575); // ln(10000)/32
        double ang = (double)pos_ids[s] * invf;
        cs[t] = (float)cos(ang);
        sn[t] = (float)sin(ang);
    }
    __syncthreads();
    if (t < 32) {
        float x0 = qackv[(long)s * QKVN + 2048 + 2 * t];
        float x1 = qackv[(long)s * QKVN + 2048 + 2 * t + 1];
        kr[t]      = x0 * cs[t] - x1 * sn[t];
        kr[32 + t] = x1 * cs[t] + x0 * sn[t];
    }
    __syncthreads();
    for (int idx = t; idx < 512; idx += 256) {
        int h = idx >> 5, j = idx & 31;
        const float* qb = qin + (long)s * 3072 + h * 192;
        float x0 = qb[128 + 2 * j], x1 = qb[128 + 2 * j + 1];
        float a = x0 * cs[j] - x1 * sn[j];
        float b = x1 * cs[j] + x0 * sn[j];
        long o = ((long)h * SEQ + s) * 192;
        __nv_bfloat16 ha = __float2bfloat16(a), hb = __float2bfloat16(b);
        qh[o + 128 + j] = ha; ql[o + 128 + j] = __float2bfloat16(a - __bfloat162float(ha));
        qh[o + 160 + j] = hb; ql[o + 160 + j] = __float2bfloat16(b - __bfloat162float(hb));
    }
    for (int idx = t; idx < 2048; idx += 256) {
        int h = idx >> 7, d = idx & 127;
        float v = qin[(long)s * 3072 + h * 192 + d];
        long o = ((long)h * SEQ + s) * 192 + d;
        __nv_bfloat16 hv = __float2bfloat16(v);
        qh[o] = hv; ql[o] = __float2bfloat16(v - __bfloat162float(hv));
    }
    for (int idx = t; idx < 16 * 192; idx += 256) {
        int h = idx / 192, d = idx - h * 192;
        float v = (d < 128) ? kvin[(long)s * 4096 + h * 256 + d] : kr[d - 128];
        long o = ((long)h * SEQ + s) * 192 + d;
        kout[o] = v;
        __nv_bfloat16 hv = __float2bfloat16(v);
        kh[o] = hv; kl[o] = __float2bfloat16(v - __bfloat162float(hv));
    }
    for (int idx = t; idx < 2048; idx += 256) {
        int h = idx >> 7, d = idx & 127;
        float v = kvin[(long)s * 4096 + h * 256 + 128 + d];
        long o = ((long)h * SEQ + s) * 128 + d;
        vout[o] = v;
        __nv_bfloat16 hv = __float2bfloat16(v);
        vh[o] = hv; vl[o] = __float2bfloat16(v - __bfloat162float(hv));
    }
}

// ---------------- flash attention: 128-row Q tile, 32-key stages --------------
#define FPADB 400   // (192+8)*2 bytes per smem row (Q/K)
#define VPADB 272   // (128+8)*2 bytes per smem row (V)
#define QT_B (128 * FPADB)          // 51200
#define KT_B (32 * FPADB)           // 12800
#define VT_B (32 * VPADB)           // 8704
#define KV_BASE (2 * QT_B)          // 102400
#define KV_STAGE (2 * KT_B + 2 * VT_B)  // 43008
#define FLASH_SMEM (KV_BASE + 2 * KV_STAGE)  // 188416

__device__ __forceinline__ void f_fill_kv(uint32_t dst,
                                          const __nv_bfloat16* __restrict__ Kh,
                                          const __nv_bfloat16* __restrict__ Kl,
                                          const __nv_bfloat16* __restrict__ Vh,
                                          const __nv_bfloat16* __restrict__ Vl,
                                          long k0, int t)
{
#pragma unroll
    for (int i = 0; i < 3; ++i) {               // 768 ids: K 32 rows x 24 chunks
        int id = t + 256 * i;
        int row = id / 24, ch = id % 24;
        cpa16(dst + row * FPADB + ch * 16, Kh + (k0 + row) * 192 + ch * 8, 16);
        cpa16(dst + KT_B + row * FPADB + ch * 16, Kl + (k0 + row) * 192 + ch * 8, 16);
    }
#pragma unroll
    for (int i = 0; i < 2; ++i) {               // 512 ids: V 32 rows x 16 chunks
        int id = t + 256 * i;
        int row = id >> 4, ch = id & 15;
        cpa16(dst + 2 * KT_B + row * VPADB + ch * 16, Vh + (k0 + row) * 128 + ch * 8, 16);
        cpa16(dst + 2 * KT_B + VT_B + row * VPADB + ch * 16, Vl + (k0 + row) * 128 + ch * 8, 16);
    }
}

__global__ __launch_bounds__(256, 1)
void flash_mma(const __nv_bfloat16* __restrict__ Qh_g, const __nv_bfloat16* __restrict__ Ql_g,
               const __nv_bfloat16* __restrict__ Kh_g, const __nv_bfloat16* __restrict__ Kl_g,
               const __nv_bfloat16* __restrict__ Vh_g, const __nv_bfloat16* __restrict__ Vl_g,
               __nv_bfloat16* __restrict__ Oh_g, __nv_bfloat16* __restrict__ Ol_g)
{
    extern __shared__ __align__(128) char smem[];
    uint32_t sb = smem_u32(smem);
    int qt = (int)gridDim.x - 1 - (int)blockIdx.x;   // LPT: longest CTAs first
    int h = blockIdx.y;
    int q0 = qt * 128;
    int t = threadIdx.x;
    int warp = t >> 5, lane = t & 31;

    const __nv_bfloat16* Kgh = Kh_g + (long)h * SEQ * 192;
    const __nv_bfloat16* Kgl = Kl_g + (long)h * SEQ * 192;
    const __nv_bfloat16* Vgh = Vh_g + (long)h * SEQ * 128;
    const __nv_bfloat16* Vgl = Vl_g + (long)h * SEQ * 128;

    // Q tile: 128 rows x 192, hi+lo
    {
        const __nv_bfloat16* qg = Qh_g + ((long)h * SEQ + q0) * 192;
        const __nv_bfloat16* qg2 = Ql_g + ((long)h * SEQ + q0) * 192;
#pragma unroll
        for (int i = 0; i < 12; ++i) {          // 3072 ids
            int id = t + 256 * i;
            int row = id / 24, ch = id % 24;
            cpa16(sb + row * FPADB + ch * 16, qg + (long)row * 192 + ch * 8, 16);
            cpa16(sb + QT_B + row * FPADB + ch * 16, qg2 + (long)row * 192 + ch * 8, 16);
        }
        CP_COMMIT();
    }
    // KV stage 0
    f_fill_kv(sb + KV_BASE, Kgh, Kgl, Vgh, Vgl, 0, t);
    CP_COMMIT();

    float o[16][4];
#pragma unroll
    for (int i = 0; i < 16; i++)
#pragma unroll
        for (int r = 0; r < 4; r++) o[i][r] = 0.f;
    float mrow[2] = {-1e30f, -1e30f};
    float lrow[2] = {0.f, 0.f};

    uint32_t qoff = (uint32_t)((warp * 16 + (lane & 15)) * FPADB + (lane >> 4) * 16);
    uint32_t koff = (uint32_t)(((lane & 7) + ((lane >> 4) << 3)) * FPADB +
                               ((lane >> 3) & 1) * 16);
    uint32_t voff = (uint32_t)(((lane & 7) + (((lane >> 3) & 1) << 3)) * VPADB +
                               ((lane >> 4) << 3) * 2);

    int rA = (lane >> 2);
    int colq = (lane & 3) * 2;
    int rowA = q0 + warp * 16 + rA;
    int rowB = rowA + 8;
    int nkt = 4 * qt + 4;

    for (int kt = 0; kt < nkt; ++kt) {
        __syncthreads();
        if (kt + 1 < nkt)
            f_fill_kv(sb + KV_BASE + ((kt + 1) & 1) * KV_STAGE, Kgh, Kgl, Vgh, Vgl,
                      (long)(kt + 1) * 32, t);
        CP_COMMIT();
        CP_WAIT(1);
        __syncthreads();

        int k0 = kt * 32;
        uint32_t kvb = sb + KV_BASE + (kt & 1) * KV_STAGE;

        // ---- S = Q @ K^T  (16 rows x 32 keys per warp) ----
        float sc[4][4];
#pragma unroll
        for (int j = 0; j < 4; j++)
#pragma unroll
            for (int r = 0; r < 4; r++) sc[j][r] = 0.f;

#pragma unroll 1
        for (int k16 = 0; k16 < 12; ++k16) {
            uint32_t qfh[4], qfl[4];
            uint32_t addr = sb + qoff + k16 * 32;
            ldsm4(qfh[0], qfh[1], qfh[2], qfh[3], addr);
            ldsm4(qfl[0], qfl[1], qfl[2], qfl[3], addr + QT_B);
            uint32_t kbh[4][2], kbl[4][2];
#pragma unroll
            for (int j2 = 0; j2 < 2; ++j2) {
                uint32_t ka = kvb + koff + j2 * 16 * FPADB + k16 * 32;
                uint32_t r0, r1, r2, r3;
                ldsm4(r0, r1, r2, r3, ka);
                kbh[2 * j2][0] = r0; kbh[2 * j2][1] = r1;
                kbh[2 * j2 + 1][0] = r2; kbh[2 * j2 + 1][1] = r3;
                ldsm4(r0, r1, r2, r3, ka + KT_B);
                kbl[2 * j2][0] = r0; kbl[2 * j2][1] = r1;
                kbl[2 * j2 + 1][0] = r2; kbl[2 * j2 + 1][1] = r3;
            }
#pragma unroll
            for (int j = 0; j < 4; ++j) {
                mma16816(sc[j], qfh[0], qfh[1], qfh[2], qfh[3], kbh[j][0], kbh[j][1]);
                mma16816(sc[j], qfh[0], qfh[1], qfh[2], qfh[3], kbl[j][0], kbl[j][1]);
                mma16816(sc[j], qfl[0], qfl[1], qfl[2], qfl[3], kbh[j][0], kbh[j][1]);
            }
        }

        bool diag = (kt >= 4 * qt);
#pragma unroll
        for (int j = 0; j < 4; ++j) {
#pragma unroll
            for (int r = 0; r < 4; r++) sc[j][r] *= SM_SCALE;
            if (diag) {
                int col = k0 + j * 8 + colq;
                if (col > rowA)     sc[j][0] = -1e30f;
                if (col + 1 > rowA) sc[j][1] = -1e30f;
                if (col > rowB)     sc[j][2] = -1e30f;
                if (col + 1 > rowB) sc[j][3] = -1e30f;
            }
        }
        float mxa = -1e30f, mxb = -1e30f;
#pragma unroll
        for (int j = 0; j < 4; ++j) {
            mxa = fmaxf(mxa, fmaxf(sc[j][0], sc[j][1]));
            mxb = fmaxf(mxb, fmaxf(sc[j][2], sc[j][3]));
        }
        mxa = fmaxf(mxa, __shfl_xor_sync(0xffffffffu, mxa, 1));
        mxa = fmaxf(mxa, __shfl_xor_sync(0xffffffffu, mxa, 2));
        mxb = fmaxf(mxb, __shfl_xor_sync(0xffffffffu, mxb, 1));
        mxb = fmaxf(mxb, __shfl_xor_sync(0xffffffffu, mxb, 2));
        float mna = fmaxf(mrow[0], mxa), mnb = fmaxf(mrow[1], mxb);
        float ala = __expf(mrow[0] - mna), alb = __expf(mrow[1] - mnb);
        mrow[0] = mna; mrow[1] = mnb;

        float suma = 0.f, sumb = 0.f;
#pragma unroll
        for (int j = 0; j < 4; ++j) {
            sc[j][0] = __expf(sc[j][0] - mna);
            sc[j][1] = __expf(sc[j][1] - mna);
            sc[j][2] = __expf(sc[j][2] - mnb);
            sc[j][3] = __expf(sc[j][3] - mnb);
            suma += sc[j][0] + sc[j][1];
            sumb += sc[j][2] + sc[j][3];
        }
        suma += __shfl_xor_sync(0xffffffffu, suma, 1);
        suma += __shfl_xor_sync(0xffffffffu, suma, 2);
        sumb += __shfl_xor_sync(0xffffffffu, sumb, 1);
        sumb += __shfl_xor_sync(0xffffffffu, sumb, 2);
        lrow[0] = lrow[0] * ala + suma;
        lrow[1] = lrow[1] * alb + sumb;
#pragma unroll
        for (int nb = 0; nb < 16; ++nb) {
            o[nb][0] *= ala; o[nb][1] *= ala;
            o[nb][2] *= alb; o[nb][3] *= alb;
        }

        uint32_t pah[2][4], pal[2][4];
#pragma unroll
        for (int j = 0; j < 2; ++j) {
            split2(sc[2 * j][0],     sc[2 * j][1],     pah[j][0], pal[j][0]);
            split2(sc[2 * j][2],     sc[2 * j][3],     pah[j][1], pal[j][1]);
            split2(sc[2 * j + 1][0], sc[2 * j + 1][1], pah[j][2], pal[j][2]);
            split2(sc[2 * j + 1][2], sc[2 * j + 1][3], pah[j][3], pal[j][3]);
        }

        // ---- O += P @ V ----
        uint32_t vbase = kvb + 2 * KT_B;
#pragma unroll 1
        for (int j = 0; j < 2; ++j) {
#pragma unroll
            for (int nb2 = 0; nb2 < 8; ++nb2) {
                uint32_t va = vbase + voff + j * 16 * VPADB + nb2 * 32;
                uint32_t h0, h1, h2, h3, l0, l1, l2, l3;
                ldsm4t(h0, h1, h2, h3, va);
                ldsm4t(l0, l1, l2, l3, va + VT_B);
                mma16816(o[2 * nb2],     pah[j][0], pah[j][1], pah[j][2], pah[j][3], h0, h1);
                mma16816(o[2 * nb2],     pah[j][0], pah[j][1], pah[j][2], pah[j][3], l0, l1);
                mma16816(o[2 * nb2],     pal[j][0], pal[j][1], pal[j][2], pal[j][3], h0, h1);
                mma16816(o[2 * nb2 + 1], pah[j][0], pah[j][1], pah[j][2], pah[j][3], h2, h3);
                mma16816(o[2 * nb2 + 1], pah[j][0], pah[j][1], pah[j][2], pah[j][3], l2, l3);
                mma16816(o[2 * nb2 + 1], pal[j][0], pal[j][1], pal[j][2], pal[j][3], h2, h3);
            }
        }
    }

    float inva = 1.0f / lrow[0], invb = 1.0f / lrow[1];
#pragma unroll
    for (int nb = 0; nb < 16; ++nb) {
        int col = h * 128 + nb * 8 + colq;
        uint32_t hA, lA, hB, lB;
        split2(o[nb][0] * inva, o[nb][1] * inva, hA, lA);
        split2(o[nb][2] * invb, o[nb][3] * invb, hB, lB);
        *(uint32_t*)&Oh_g[(long)rowA * 2048 + col] = hA;
        *(uint32_t*)&Ol_g[(long)rowA * 2048 + col] = lA;
        *(uint32_t*)&Oh_g[(long)rowB * 2048 + col] = hB;
        *(uint32_t*)&Ol_g[(long)rowB * 2048 + col] = lB;
    }
}

// ---------------- launch ------------------------------------------------------
extern "C" void kernel_launch(void* const* d_in, const int* in_sizes, int n_in,
                              void* d_out, int out_size)
{
    const float* hidden   = (const float*)d_in[0];
    const int*   pos      = (const int*)d_in[1];
    const float* ln_w     = (const float*)d_in[3];
    const float* wq_a     = (const float*)d_in[4];
    const float* q_a_ln   = (const float*)d_in[5];
    const float* wq_b     = (const float*)d_in[6];
    const float* wkv_a    = (const float*)d_in[7];
    const float* kv_a_ln  = (const float*)d_in[8];
    const float* wkv_b    = (const float*)d_in[9];
    const float* wo       = (const float*)d_in[10];

    float* out   = (float*)d_out;
    float* k_out = out + (long)SEQ * HIDDEN;
    float* v_out = k_out + (long)NHEADS * SEQ * QKD;

    float *p_qackv, *p_q, *p_kv;
    cudaGetSymbolAddress((void**)&p_qackv, g_qackv);
    cudaGetSymbolAddress((void**)&p_q, g_q);
    cudaGetSymbolAddress((void**)&p_kv, g_kv);

    __nv_bfloat16 *h_hi, *h_lo, *qa_hi, *qa_lo, *ckvn_hi, *ckvn_lo, *attn_hi, *attn_lo;
    __nv_bfloat16 *qf_hi, *qf_lo, *k_hi, *k_lo, *v_hi, *v_lo;
    __nv_bfloat16 *wqkva_hi, *wqkva_lo, *wqb_hi, *wqb_lo, *wkvb_hi, *wkvb_lo, *wo_hi, *wo_lo;
    cudaGetSymbolAddress((void**)&h_hi, g_h_hi);       cudaGetSymbolAddress((void**)&h_lo, g_h_lo);
    cudaGetSymbolAddress((void**)&qa_hi, g_qa_hi);     cudaGetSymbolAddress((void**)&qa_lo, g_qa_lo);
    cudaGetSymbolAddress((void**)&ckvn_hi, g_ckvn_hi); cudaGetSymbolAddress((void**)&ckvn_lo, g_ckvn_lo);
    cudaGetSymbolAddress((void**)&attn_hi, g_attn_hi); cudaGetSymbolAddress((void**)&attn_lo, g_attn_lo);
    cudaGetSymbolAddress((void**)&qf_hi, g_qf_hi);     cudaGetSymbolAddress((void**)&qf_lo, g_qf_lo);
    cudaGetSymbolAddress((void**)&k_hi, g_k_hi);       cudaGetSymbolAddress((void**)&k_lo, g_k_lo);
    cudaGetSymbolAddress((void**)&v_hi, g_v_hi);       cudaGetSymbolAddress((void**)&v_lo, g_v_lo);
    cudaGetSymbolAddress((void**)&wqkva_hi, g_wqkva_hi); cudaGetSymbolAddress((void**)&wqkva_lo, g_wqkva_lo);
    cudaGetSymbolAddress((void**)&wqb_hi, g_wqb_hi);   cudaGetSymbolAddress((void**)&wqb_lo, g_wqb_lo);
    cudaGetSymbolAddress((void**)&wkvb_hi, g_wkvb_hi); cudaGetSymbolAddress((void**)&wkvb_lo, g_wkvb_lo);
    cudaGetSymbolAddress((void**)&wo_hi, g_wo_hi);     cudaGetSymbolAddress((void**)&wo_lo, g_wo_lo);

    cudaFuncSetAttribute(gemm_mma, cudaFuncAttributeMaxDynamicSharedMemorySize, GEMM_SMEM);
    cudaFuncSetAttribute(gemm_dual, cudaFuncAttributeMaxDynamicSharedMemorySize, GEMM_SMEM);
    cudaFuncSetAttribute(flash_mma, cudaFuncAttributeMaxDynamicSharedMemorySize, FLASH_SMEM);

    cvt_b16<<<592, 256>>>(wq_a,  wqkva_hi, wqkva_lo, (long)QLORA * HIDDEN);
    cvt_b16<<<592, 256>>>(wkv_a, wqkva_hi + (long)QLORA * HIDDEN,
                                 wqkva_lo + (long)QLORA * HIDDEN, (long)576 * HIDDEN);
    cvt_b16<<<592, 256>>>(wq_b,  wqb_hi,  wqb_lo,  (long)3072 * QLORA);
    cvt_b16<<<592, 256>>>(wkv_b, wkvb_hi, wkvb_lo, (long)4096 * KVLORA);
    cvt_b16<<<592, 256>>>(wo,    wo_hi,   wo_lo,   (long)HIDDEN * 2048);

    rmsnorm_b16<<<SEQ, 256>>>(hidden, ln_w, h_hi, h_lo, HIDDEN, HIDDEN, HIDDEN);
    // fused q_a + ckv projection
    gemm_mma<<<dim3(17, SEQ / 128), 256, GEMM_SMEM>>>(
        h_hi, h_lo, HIDDEN, wqkva_hi, wqkva_lo, p_qackv, SEQ, QKVN, HIDDEN, nullptr, 0.f);
    rmsnorm_b16<<<SEQ, 256>>>(p_qackv, q_a_ln, qa_hi, qa_lo, QLORA, QKVN, QLORA);
    rmsnorm_b16<<<SEQ, 256>>>(p_qackv + QLORA, kv_a_ln, ckvn_hi, ckvn_lo, KVLORA, QKVN, KVLORA);
    // merged q up-proj (K=1536, long, scheduled first) + kv up-proj (K=512)
    gemm_dual<<<dim3(24 + 32, SEQ / 128), 256, GEMM_SMEM>>>(
        qa_hi, qa_lo, QLORA, wqb_hi, wqb_lo, p_q, 3072, QLORA,
        ckvn_hi, ckvn_lo, KVLORA, wkvb_hi, wkvb_lo, p_kv, 4096, KVLORA, 24);
    rope_scatter<<<SEQ, 256>>>(p_q, p_qackv, p_kv, pos, qf_hi, qf_lo,
                               k_out, k_hi, k_lo, v_out, v_hi, v_lo);
    flash_mma<<<dim3(SEQ / 128, NHEADS), 256, FLASH_SMEM>>>(
        qf_hi, qf_lo, k_hi, k_lo, v_hi, v_lo, attn_hi, attn_lo);
    gemm_mma<<<dim3(HIDDEN / 128, SEQ / 128), 256, GEMM_SMEM>>>(
        attn_hi, attn_lo, 2048, wo_hi, wo_lo, out, SEQ, HIDDEN, 2048,
        hidden, RESID_SCALE);
}

// round 7
// speedup vs baseline: 1.1216x; 1.1216x over previous
#include <cuda_runtime.h>
#include <cuda_bf16.h>
#include <math.h>
#include <stdint.h>

#define HIDDEN 5120
#define NHEADS 16
#define QLORA  1536
#define KVLORA 512
#define NOPE   128
#define ROPE_D 64
#define QKD    192
#define VDIM   128
#define SEQ    2048
#define QKVN   2112
#define SM_SCALE 0.07216878364870322f  // 192^-0.5
#define RESID_SCALE 0.125f

// ---------------- scratch ----------------------------------------------------
static __device__ float g_qackv[SEQ * QKVN];
static __device__ float g_q[SEQ * NHEADS * QKD];
static __device__ float g_kv[SEQ * 4096];

static __device__ __nv_bfloat16 g_h_hi[SEQ * HIDDEN],    g_h_lo[SEQ * HIDDEN];
static __device__ __nv_bfloat16 g_qa_hi[SEQ * QLORA],    g_qa_lo[SEQ * QLORA];
static __device__ __nv_bfloat16 g_ckvn_hi[SEQ * KVLORA], g_ckvn_lo[SEQ * KVLORA];
static __device__ __nv_bfloat16 g_attn_hi[SEQ * 2048],   g_attn_lo[SEQ * 2048];
static __device__ __nv_bfloat16 g_qf_hi[NHEADS * SEQ * QKD], g_qf_lo[NHEADS * SEQ * QKD];
static __device__ __nv_bfloat16 g_k_hi[NHEADS * SEQ * QKD],  g_k_lo[NHEADS * SEQ * QKD];
static __device__ __nv_bfloat16 g_v_hi[NHEADS * SEQ * VDIM], g_v_lo[NHEADS * SEQ * VDIM];

static __device__ __nv_bfloat16 g_wqkva_hi[QKVN * HIDDEN], g_wqkva_lo[QKVN * HIDDEN];
static __device__ __nv_bfloat16 g_wqb_hi[3072 * QLORA],    g_wqb_lo[3072 * QLORA];
static __device__ __nv_bfloat16 g_wkvb_hi[4096 * KVLORA],  g_wkvb_lo[4096 * KVLORA];
static __device__ __nv_bfloat16 g_wo_hi[HIDDEN * 2048],    g_wo_lo[HIDDEN * 2048];

// ---------------- helpers ----------------------------------------------------
__device__ __forceinline__ uint32_t smem_u32(const void* p) {
    return (uint32_t)__cvta_generic_to_shared(p);
}
__device__ __forceinline__ void cpa16(uint32_t dst, const void* src, int sz) {
    asm volatile("cp.async.cg.shared.global [%0], [%1], 16, %2;"
                 :: "r"(dst), "l"(src), "r"(sz) : "memory");
}
#define CP_COMMIT() asm volatile("cp.async.commit_group;" ::: "memory")
#define CP_WAIT(n)  asm volatile("cp.async.wait_group %0;" :: "n"(n) : "memory")

__device__ __forceinline__ void ldsm4(uint32_t& r0, uint32_t& r1, uint32_t& r2, uint32_t& r3,
                                      uint32_t addr) {
    asm volatile("ldmatrix.sync.aligned.m8n8.x4.shared.b16 {%0,%1,%2,%3}, [%4];"
                 : "=r"(r0), "=r"(r1), "=r"(r2), "=r"(r3) : "r"(addr));
}
__device__ __forceinline__ void ldsm4t(uint32_t& r0, uint32_t& r1, uint32_t& r2, uint32_t& r3,
                                       uint32_t addr) {
    asm volatile("ldmatrix.sync.aligned.m8n8.x4.trans.shared.b16 {%0,%1,%2,%3}, [%4];"
                 : "=r"(r0), "=r"(r1), "=r"(r2), "=r"(r3) : "r"(addr));
}
__device__ __forceinline__ void mma16816(float* c, uint32_t a0, uint32_t a1, uint32_t a2,
                                         uint32_t a3, uint32_t b0, uint32_t b1) {
    asm volatile(
        "mma.sync.aligned.m16n8k16.row.col.f32.bf16.bf16.f32 "
        "{%0,%1,%2,%3}, {%4,%5,%6,%7}, {%8,%9}, {%0,%1,%2,%3};"
        : "+f"(c[0]), "+f"(c[1]), "+f"(c[2]), "+f"(c[3])
        : "r"(a0), "r"(a1), "r"(a2), "r"(a3), "r"(b0), "r"(b1));
}
__device__ __forceinline__ void split2(float v0, float v1, uint32_t& hi, uint32_t& lo) {
    __nv_bfloat16 h0 = __float2bfloat16(v0), h1 = __float2bfloat16(v1);
    float r0 = v0 - __bfloat162float(h0), r1 = v1 - __bfloat162float(h1);
    __nv_bfloat162 th; th.x = h0; th.y = h1;
    hi = *reinterpret_cast<uint32_t*>(&th);
    __nv_bfloat162 tl; tl.x = __float2bfloat16(r0); tl.y = __float2bfloat16(r1);
    lo = *reinterpret_cast<uint32_t*>(&tl);
}

// ---------------- batched fp32 -> bf16 hi/lo converter ------------------------
__global__ void cvt_b16_multi(
    const float* __restrict__ x0, __nv_bfloat16* __restrict__ h0, __nv_bfloat16* __restrict__ l0, long c0,
    const float* __restrict__ x1, __nv_bfloat16* __restrict__ h1, __nv_bfloat16* __restrict__ l1, long c1,
    const float* __restrict__ x2, __nv_bfloat16* __restrict__ h2, __nv_bfloat16* __restrict__ l2, long c2,
    const float* __restrict__ x3, __nv_bfloat16* __restrict__ h3, __nv_bfloat16* __restrict__ l3, long c3,
    const float* __restrict__ x4, __nv_bfloat16* __restrict__ h4, __nv_bfloat16* __restrict__ l4, long c4)
{
    // c* are cumulative float4 counts
    for (long i = (long)blockIdx.x * blockDim.x + threadIdx.x; i < c4;
         i += (long)gridDim.x * blockDim.x) {
        const float4* xp; __nv_bfloat162* hp; __nv_bfloat162* lp; long base;
        if (i < c0)      { xp = (const float4*)x0; hp = (__nv_bfloat162*)h0; lp = (__nv_bfloat162*)l0; base = 0; }
        else if (i < c1) { xp = (const float4*)x1; hp = (__nv_bfloat162*)h1; lp = (__nv_bfloat162*)l1; base = c0; }
        else if (i < c2) { xp = (const float4*)x2; hp = (__nv_bfloat162*)h2; lp = (__nv_bfloat162*)l2; base = c1; }
        else if (i < c3) { xp = (const float4*)x3; hp = (__nv_bfloat162*)h3; lp = (__nv_bfloat162*)l3; base = c2; }
        else             { xp = (const float4*)x4; hp = (__nv_bfloat162*)h4; lp = (__nv_bfloat162*)l4; base = c3; }
        long j = i - base;
        float4 v = xp[j];
        __nv_bfloat162 ha; ha.x = __float2bfloat16(v.x); ha.y = __float2bfloat16(v.y);
        __nv_bfloat162 hb; hb.x = __float2bfloat16(v.z); hb.y = __float2bfloat16(v.w);
        __nv_bfloat162 la; la.x = __float2bfloat16(v.x - __bfloat162float(ha.x));
        la.y = __float2bfloat16(v.y - __bfloat162float(ha.y));
        __nv_bfloat162 lb; lb.x = __float2bfloat16(v.z - __bfloat162float(hb.x));
        lb.y = __float2bfloat16(v.w - __bfloat162float(hb.y));
        hp[2 * j] = ha; hp[2 * j + 1] = hb;
        lp[2 * j] = la; lp[2 * j + 1] = lb;
    }
}

__global__ void rmsnorm_b16(const float* __restrict__ x, const float* __restrict__ w,
                            __nv_bfloat16* __restrict__ hi, __nv_bfloat16* __restrict__ lo,
                            int cols, int strideIn, int strideOut)
{
    int row = blockIdx.x;
    int t = threadIdx.x;
    const float4* xr = (const float4*)(x + (long)row * strideIn);
    const float4* w4 = (const float4*)w;
    int c4 = cols >> 2;
    float ss = 0.f;
    for (int c = t; c < c4; c += 256) {
        float4 v = xr[c];
        ss = fmaf(v.x, v.x, fmaf(v.y, v.y, fmaf(v.z, v.z, fmaf(v.w, v.w, ss))));
    }
    __shared__ float red[256];
    red[t] = ss; __syncthreads();
    for (int s = 128; s > 0; s >>= 1) { if (t < s) red[t] += red[t + s]; __syncthreads(); }
    float scale = rsqrtf(red[0] / (float)cols + 1e-6f);
    __nv_bfloat162* hr = (__nv_bfloat162*)(hi + (long)row * strideOut);
    __nv_bfloat162* lr = (__nv_bfloat162*)(lo + (long)row * strideOut);
    for (int c = t; c < c4; c += 256) {
        float4 v = xr[c];
        float4 wv = w4[c];
        float a = v.x * scale * wv.x, b = v.y * scale * wv.y;
        float d = v.z * scale * wv.z, e = v.w * scale * wv.w;
        __nv_bfloat162 ha; ha.x = __float2bfloat16(a); ha.y = __float2bfloat16(b);
        __nv_bfloat162 hb; hb.x = __float2bfloat16(d); hb.y = __float2bfloat16(e);
        __nv_bfloat162 la; la.x = __float2bfloat16(a - __bfloat162float(ha.x));
        la.y = __float2bfloat16(b - __bfloat162float(ha.y));
        __nv_bfloat162 lb; lb.x = __float2bfloat16(d - __bfloat162float(hb.x));
        lb.y = __float2bfloat16(e - __bfloat162float(hb.y));
        hr[2 * c] = ha; hr[2 * c + 1] = hb;
        lr[2 * c] = la; lr[2 * c + 1] = lb;
    }
}

// ---------------- mma.sync bf16x3 GEMM: swizzled 64B rows, 3 stages -----------
// CTA tile 128x128, Kc=32, 256 threads (8 warps 2x4), warp tile 64x32.
// Swizzle: chunk' = chunk ^ ((row>>1)&3) over 4 chunks of 16B per 64B row.
#define GT_BYTES (128 * 64)         // 8192
#define GS_BYTES (4 * GT_BYTES)     // 32768 per stage
#define GSTAGES 3
#define GEMM_SMEM (GSTAGES * GS_BYTES)  // 98304; 2 CTAs/SM = 192KB

__device__ __forceinline__ void g_fill(uint32_t dstBase, const __nv_bfloat16* __restrict__ src,
                                       long ld, int rmax, int t)
{
#pragma unroll
    for (int i = 0; i < 2; ++i) {
        int id = t + 256 * i;
        int row = id >> 2, c = id & 3;
        bool ok = row < rmax;
        const __nv_bfloat16* g = src + (long)(ok ? row : 0) * ld + c * 8;
        uint32_t cs = (uint32_t)(c ^ ((row >> 1) & 3));
        cpa16(dstBase + row * 64 + cs * 16, g, ok ? 16 : 0);
    }
}

__device__ __forceinline__ void gemm_core(
    const __nv_bfloat16* __restrict__ Ah, const __nv_bfloat16* __restrict__ Al, int lda,
    const __nv_bfloat16* __restrict__ Bh, const __nv_bfloat16* __restrict__ Bl,
    float* __restrict__ C, int M, int N, int K,
    const float* __restrict__ D, float beta, int bx, int by, char* smem)
{
    uint32_t sb = smem_u32(smem);
    int t = threadIdx.x;
    int warp = t >> 5, lane = t & 31;
    int wm = warp >> 2, wn = warp & 3;
    int n0 = bx * 128, m0 = by * 128;
    int nc = K / 32;

    float acc[4][4][4];
#pragma unroll
    for (int i = 0; i < 4; i++)
#pragma unroll
        for (int j = 0; j < 4; j++)
#pragma unroll
            for (int r = 0; r < 4; r++) acc[i][j][r] = 0.f;

    // prologue: chunks 0,1 into stages 0,1
#pragma unroll
    for (int s = 0; s < 2; ++s) {
        uint32_t b0 = sb + s * GS_BYTES;
        int kc0 = s * 32;
        g_fill(b0 + 0 * GT_BYTES, Ah + (long)m0 * lda + kc0, lda, M - m0, t);
        g_fill(b0 + 1 * GT_BYTES, Al + (long)m0 * lda + kc0, lda, M - m0, t);
        g_fill(b0 + 2 * GT_BYTES, Bh + (long)n0 * K + kc0, K, N - n0, t);
        g_fill(b0 + 3 * GT_BYTES, Bl + (long)n0 * K + kc0, K, N - n0, t);
        CP_COMMIT();
    }

    int aRow = wm * 64 + (lane & 15);
    int aCl = lane >> 4;
    int bRow = wn * 32 + (lane & 7) + ((lane >> 4) << 3);
    int bCl = (lane >> 3) & 1;

    int stage = 0;
    for (int c = 0; c < nc; ++c) {
        CP_WAIT(1);
        __syncthreads();
        if (c + 2 < nc) {
            int ps = stage + 2; if (ps >= GSTAGES) ps -= GSTAGES;
            uint32_t bn = sb + ps * GS_BYTES;
            int kc0 = (c + 2) * 32;
            g_fill(bn + 0 * GT_BYTES, Ah + (long)m0 * lda + kc0, lda, M - m0, t);
            g_fill(bn + 1 * GT_BYTES, Al + (long)m0 * lda + kc0, lda, M - m0, t);
            g_fill(bn + 2 * GT_BYTES, Bh + (long)n0 * K + kc0, K, N - n0, t);
            g_fill(bn + 3 * GT_BYTES, Bl + (long)n0 * K + kc0, K, N - n0, t);
        }
        CP_COMMIT();

        uint32_t base = sb + stage * GS_BYTES;
#pragma unroll
        for (int k16 = 0; k16 < 2; ++k16) {
            uint32_t ah[4][4], al_[4][4];
#pragma unroll
            for (int im = 0; im < 4; ++im) {
                int r = aRow + im * 16;
                uint32_t addr = base + r * 64 + (((k16 * 2 + aCl) ^ ((r >> 1) & 3)) << 4);
                ldsm4(ah[im][0], ah[im][1], ah[im][2], ah[im][3], addr);
                ldsm4(al_[im][0], al_[im][1], al_[im][2], al_[im][3], addr + GT_BYTES);
            }
            uint32_t bh[4][2], bl[4][2];
#pragma unroll
            for (int j2 = 0; j2 < 2; ++j2) {
                int r = bRow + j2 * 16;
                uint32_t addr = base + 2 * GT_BYTES + r * 64 +
                                (((k16 * 2 + bCl) ^ ((r >> 1) & 3)) << 4);
                uint32_t r0, r1, r2, r3;
                ldsm4(r0, r1, r2, r3, addr);
                bh[2 * j2][0] = r0; bh[2 * j2][1] = r1;
                bh[2 * j2 + 1][0] = r2; bh[2 * j2 + 1][1] = r3;
                ldsm4(r0, r1, r2, r3, addr + GT_BYTES);
                bl[2 * j2][0] = r0; bl[2 * j2][1] = r1;
                bl[2 * j2 + 1][0] = r2; bl[2 * j2 + 1][1] = r3;
            }
#pragma unroll
            for (int im = 0; im < 4; ++im)
#pragma unroll
                for (int jn = 0; jn < 4; ++jn) {
                    mma16816(acc[im][jn], ah[im][0], ah[im][1], ah[im][2], ah[im][3],
                             bh[jn][0], bh[jn][1]);
                    mma16816(acc[im][jn], ah[im][0], ah[im][1], ah[im][2], ah[im][3],
                             bl[jn][0], bl[jn][1]);
                    mma16816(acc[im][jn], al_[im][0], al_[im][1], al_[im][2], al_[im][3],
                             bh[jn][0], bh[jn][1]);
                }
        }
        if (++stage >= GSTAGES) stage = 0;
    }

#pragma unroll
    for (int im = 0; im < 4; ++im) {
        int row0 = m0 + wm * 64 + im * 16 + (lane >> 2);
#pragma unroll
        for (int jn = 0; jn < 4; ++jn) {
            int col = n0 + wn * 32 + jn * 8 + (lane & 3) * 2;
            if (col < N) {
                float2 v0 = make_float2(acc[im][jn][0], acc[im][jn][1]);
                float2 v1 = make_float2(acc[im][jn][2], acc[im][jn][3]);
                if (D) {
                    float2 d0 = *(const float2*)&D[(long)row0 * N + col];
                    float2 d1 = *(const float2*)&D[(long)(row0 + 8) * N + col];
                    v0.x = fmaf(beta, d0.x, v0.x); v0.y = fmaf(beta, d0.y, v0.y);
                    v1.x = fmaf(beta, d1.x, v1.x); v1.y = fmaf(beta, d1.y, v1.y);
                }
                *(float2*)&C[(long)row0 * N + col] = v0;
                *(float2*)&C[(long)(row0 + 8) * N + col] = v1;
            }
        }
    }
}

__global__ __launch_bounds__(256, 2)
void gemm_mma(const __nv_bfloat16* __restrict__ Ah, const __nv_bfloat16* __restrict__ Al, int lda,
              const __nv_bfloat16* __restrict__ Bh, const __nv_bfloat16* __restrict__ Bl,
              float* __restrict__ C, int M, int N, int K,
              const float* __restrict__ D, float beta)
{
    extern __shared__ __align__(128) char smem[];
    gemm_core(Ah, Al, lda, Bh, Bl, C, M, N, K, D, beta, blockIdx.x, blockIdx.y, smem);
}

__global__ __launch_bounds__(256, 2)
void gemm_dual(const __nv_bfloat16* __restrict__ A1h, const __nv_bfloat16* __restrict__ A1l,
               int lda1, const __nv_bfloat16* __restrict__ B1h,
               const __nv_bfloat16* __restrict__ B1l, float* __restrict__ C1, int N1, int K1,
               const __nv_bfloat16* __restrict__ A2h, const __nv_bfloat16* __restrict__ A2l,
               int lda2, const __nv_bfloat16* __restrict__ B2h,
               const __nv_bfloat16* __restrict__ B2l, float* __restrict__ C2, int N2, int K2,
               int split)
{
    extern __shared__ __align__(128) char smem[];
    if ((int)blockIdx.x < split)
        gemm_core(A1h, A1l, lda1, B1h, B1l, C1, SEQ, N1, K1, nullptr, 0.f,
                  blockIdx.x, blockIdx.y, smem);
    else
        gemm_core(A2h, A2l, lda2, B2h, B2l, C2, SEQ, N2, K2, nullptr, 0.f,
                  blockIdx.x - split, blockIdx.y, smem);
}

// ---------------- RoPE + scatter ----------------------------------------------
__global__ void rope_scatter(const float* __restrict__ qin,    // [s][3072]
                             const float* __restrict__ qackv,  // [s][2112]
                             const float* __restrict__ kvin,   // [s][4096]
                             const int* __restrict__ pos_ids,
                             __nv_bfloat16* __restrict__ qh, __nv_bfloat16* __restrict__ ql,
                             float* __restrict__ kout,
                             __nv_bfloat16* __restrict__ kh, __nv_bfloat16* __restrict__ kl,
                             float* __restrict__ vout,
                             __nv_bfloat16* __restrict__ vh, __nv_bfloat16* __restrict__ vl)
{
    int s = blockIdx.x;
    int t = threadIdx.x;
    __shared__ float cs[32], sn[32], kr[64];
    if (t < 32) {
        double invf = exp(-(double)t * 0.28782313662425575); // ln(10000)/32
        double ang = (double)pos_ids[s] * invf;
        cs[t] = (float)cos(ang);
        sn[t] = (float)sin(ang);
    }
    __syncthreads();
    if (t < 32) {
        float x0 = qackv[(long)s * QKVN + 2048 + 2 * t];
        float x1 = qackv[(long)s * QKVN + 2048 + 2 * t + 1];
        kr[t]      = x0 * cs[t] - x1 * sn[t];
        kr[32 + t] = x1 * cs[t] + x0 * sn[t];
    }
    __syncthreads();
    for (int idx = t; idx < 512; idx += 256) {
        int h = idx >> 5, j = idx & 31;
        const float* qb = qin + (long)s * 3072 + h * 192;
        float x0 = qb[128 + 2 * j], x1 = qb[128 + 2 * j + 1];
        float a = x0 * cs[j] - x1 * sn[j];
        float b = x1 * cs[j] + x0 * sn[j];
        long o = ((long)h * SEQ + s) * 192;
        __nv_bfloat16 ha = __float2bfloat16(a), hb = __float2bfloat16(b);
        qh[o + 128 + j] = ha; ql[o + 128 + j] = __float2bfloat16(a - __bfloat162float(ha));
        qh[o + 160 + j] = hb; ql[o + 160 + j] = __float2bfloat16(b - __bfloat162float(hb));
    }
    for (int idx = t; idx < 2048; idx += 256) {
        int h = idx >> 7, d = idx & 127;
        float v = qin[(long)s * 3072 + h * 192 + d];
        long o = ((long)h * SEQ + s) * 192 + d;
        __nv_bfloat16 hv = __float2bfloat16(v);
        qh[o] = hv; ql[o] = __float2bfloat16(v - __bfloat162float(hv));
    }
    for (int idx = t; idx < 16 * 192; idx += 256) {
        int h = idx / 192, d = idx - h * 192;
        float v = (d < 128) ? kvin[(long)s * 4096 + h * 256 + d] : kr[d - 128];
        long o = ((long)h * SEQ + s) * 192 + d;
        kout[o] = v;
        __nv_bfloat16 hv = __float2bfloat16(v);
        kh[o] = hv; kl[o] = __float2bfloat16(v - __bfloat162float(hv));
    }
    for (int idx = t; idx < 2048; idx += 256) {
        int h = idx >> 7, d = idx & 127;
        float v = kvin[(long)s * 4096 + h * 256 + 128 + d];
        long o = ((long)h * SEQ + s) * 128 + d;
        vout[o] = v;
        __nv_bfloat16 hv = __float2bfloat16(v);
        vh[o] = hv; vl[o] = __float2bfloat16(v - __bfloat162float(hv));
    }
}

// ---------------- flash attention: 128-row Q tile, 32-key stages --------------
#define FPADB 400   // (192+8)*2 bytes per smem row (Q/K)
#define VPADB 272   // (128+8)*2 bytes per smem row (V)
#define QT_B (128 * FPADB)          // 51200
#define KT_B (32 * FPADB)           // 12800
#define VT_B (32 * VPADB)           // 8704
#define KV_BASE (2 * QT_B)          // 102400
#define KV_STAGE (2 * KT_B + 2 * VT_B)  // 43008
#define FLASH_SMEM (KV_BASE + 2 * KV_STAGE)  // 188416

__device__ __forceinline__ void f_fill_kv(uint32_t dst,
                                          const __nv_bfloat16* __restrict__ Kh,
                                          const __nv_bfloat16* __restrict__ Kl,
                                          const __nv_bfloat16* __restrict__ Vh,
                                          const __nv_bfloat16* __restrict__ Vl,
                                          long k0, int t)
{
#pragma unroll
    for (int i = 0; i < 3; ++i) {
        int id = t + 256 * i;
        int row = id / 24, ch = id % 24;
        cpa16(dst + row * FPADB + ch * 16, Kh + (k0 + row) * 192 + ch * 8, 16);
        cpa16(dst + KT_B + row * FPADB + ch * 16, Kl + (k0 + row) * 192 + ch * 8, 16);
    }
#pragma unroll
    for (int i = 0; i < 2; ++i) {
        int id = t + 256 * i;
        int row = id >> 4, ch = id & 15;
        cpa16(dst + 2 * KT_B + row * VPADB + ch * 16, Vh + (k0 + row) * 128 + ch * 8, 16);
        cpa16(dst + 2 * KT_B + VT_B + row * VPADB + ch * 16, Vl + (k0 + row) * 128 + ch * 8, 16);
    }
}

__global__ __launch_bounds__(256, 1)
void flash_mma(const __nv_bfloat16* __restrict__ Qh_g, const __nv_bfloat16* __restrict__ Ql_g,
               const __nv_bfloat16* __restrict__ Kh_g, const __nv_bfloat16* __restrict__ Kl_g,
               const __nv_bfloat16* __restrict__ Vh_g, const __nv_bfloat16* __restrict__ Vl_g,
               __nv_bfloat16* __restrict__ Oh_g, __nv_bfloat16* __restrict__ Ol_g)
{
    extern __shared__ __align__(128) char smem[];
    uint32_t sb = smem_u32(smem);
    int qt = (int)gridDim.x - 1 - (int)blockIdx.x;   // LPT: longest CTAs first
    int h = blockIdx.y;
    int q0 = qt * 128;
    int t = threadIdx.x;
    int warp = t >> 5, lane = t & 31;

    const __nv_bfloat16* Kgh = Kh_g + (long)h * SEQ * 192;
    const __nv_bfloat16* Kgl = Kl_g + (long)h * SEQ * 192;
    const __nv_bfloat16* Vgh = Vh_g + (long)h * SEQ * 128;
    const __nv_bfloat16* Vgl = Vl_g + (long)h * SEQ * 128;

    {
        const __nv_bfloat16* qg = Qh_g + ((long)h * SEQ + q0) * 192;
        const __nv_bfloat16* qg2 = Ql_g + ((long)h * SEQ + q0) * 192;
#pragma unroll
        for (int i = 0; i < 12; ++i) {
            int id = t + 256 * i;
            int row = id / 24, ch = id % 24;
            cpa16(sb + row * FPADB + ch * 16, qg + (long)row * 192 + ch * 8, 16);
            cpa16(sb + QT_B + row * FPADB + ch * 16, qg2 + (long)row * 192 + ch * 8, 16);
        }
        CP_COMMIT();
    }
    f_fill_kv(sb + KV_BASE, Kgh, Kgl, Vgh, Vgl, 0, t);
    CP_COMMIT();

    float o[16][4];
#pragma unroll
    for (int i = 0; i < 16; i++)
#pragma unroll
        for (int r = 0; r < 4; r++) o[i][r] = 0.f;
    float mrow[2] = {-1e30f, -1e30f};
    float lrow[2] = {0.f, 0.f};

    uint32_t qoff = (uint32_t)((warp * 16 + (lane & 15)) * FPADB + (lane >> 4) * 16);
    uint32_t koff = (uint32_t)(((lane & 7) + ((lane >> 4) << 3)) * FPADB +
                               ((lane >> 3) & 1) * 16);
    uint32_t voff = (uint32_t)(((lane & 7) + (((lane >> 3) & 1) << 3)) * VPADB +
                               ((lane >> 4) << 3) * 2);

    int rA = (lane >> 2);
    int colq = (lane & 3) * 2;
    int rowA = q0 + warp * 16 + rA;
    int rowB = rowA + 8;
    int nkt = 4 * qt + 4;

    for (int kt = 0; kt < nkt; ++kt) {
        __syncthreads();
        if (kt + 1 < nkt)
            f_fill_kv(sb + KV_BASE + ((kt + 1) & 1) * KV_STAGE, Kgh, Kgl, Vgh, Vgl,
                      (long)(kt + 1) * 32, t);
        CP_COMMIT();
        CP_WAIT(1);
        __syncthreads();

        int k0 = kt * 32;
        uint32_t kvb = sb + KV_BASE + (kt & 1) * KV_STAGE;

        float sc[4][4];
#pragma unroll
        for (int j = 0; j < 4; j++)
#pragma unroll
            for (int r = 0; r < 4; r++) sc[j][r] = 0.f;

#pragma unroll 1
        for (int k16 = 0; k16 < 12; ++k16) {
            uint32_t qfh[4], qfl[4];
            uint32_t addr = sb + qoff + k16 * 32;
            ldsm4(qfh[0], qfh[1], qfh[2], qfh[3], addr);
            ldsm4(qfl[0], qfl[1], qfl[2], qfl[3], addr + QT_B);
            uint32_t kbh[4][2], kbl[4][2];
#pragma unroll
            for (int j2 = 0; j2 < 2; ++j2) {
                uint32_t ka = kvb + koff + j2 * 16 * FPADB + k16 * 32;
                uint32_t r0, r1, r2, r3;
                ldsm4(r0, r1, r2, r3, ka);
                kbh[2 * j2][0] = r0; kbh[2 * j2][1] = r1;
                kbh[2 * j2 + 1][0] = r2; kbh[2 * j2 + 1][1] = r3;
                ldsm4(r0, r1, r2, r3, ka + KT_B);
                kbl[2 * j2][0] = r0; kbl[2 * j2][1] = r1;
                kbl[2 * j2 + 1][0] = r2; kbl[2 * j2 + 1][1] = r3;
            }
#pragma unroll
            for (int j = 0; j < 4; ++j) {
                mma16816(sc[j], qfh[0], qfh[1], qfh[2], qfh[3], kbh[j][0], kbh[j][1]);
                mma16816(sc[j], qfh[0], qfh[1], qfh[2], qfh[3], kbl[j][0], kbl[j][1]);
                mma16816(sc[j], qfl[0], qfl[1], qfl[2], qfl[3], kbh[j][0], kbh[j][1]);
            }
        }

        bool diag = (kt >= 4 * qt);
#pragma unroll
        for (int j = 0; j < 4; ++j) {
#pragma unroll
            for (int r = 0; r < 4; r++) sc[j][r] *= SM_SCALE;
            if (diag) {
                int col = k0 + j * 8 + colq;
                if (col > rowA)     sc[j][0] = -1e30f;
                if (col + 1 > rowA) sc[j][1] = -1e30f;
                if (col > rowB)     sc[j][2] = -1e30f;
                if (col + 1 > rowB) sc[j][3] = -1e30f;
            }
        }
        float mxa = -1e30f, mxb = -1e30f;
#pragma unroll
        for (int j = 0; j < 4; ++j) {
            mxa = fmaxf(mxa, fmaxf(sc[j][0], sc[j][1]));
            mxb = fmaxf(mxb, fmaxf(sc[j][2], sc[j][3]));
        }
        mxa = fmaxf(mxa, __shfl_xor_sync(0xffffffffu, mxa, 1));
        mxa = fmaxf(mxa, __shfl_xor_sync(0xffffffffu, mxa, 2));
        mxb = fmaxf(mxb, __shfl_xor_sync(0xffffffffu, mxb, 1));
        mxb = fmaxf(mxb, __shfl_xor_sync(0xffffffffu, mxb, 2));
        float mna = fmaxf(mrow[0], mxa), mnb = fmaxf(mrow[1], mxb);
        float ala = __expf(mrow[0] - mna), alb = __expf(mrow[1] - mnb);
        mrow[0] = mna; mrow[1] = mnb;

        float suma = 0.f, sumb = 0.f;
#pragma unroll
        for (int j = 0; j < 4; ++j) {
            sc[j][0] = __expf(sc[j][0] - mna);
            sc[j][1] = __expf(sc[j][1] - mna);
            sc[j][2] = __expf(sc[j][2] - mnb);
            sc[j][3] = __expf(sc[j][3] - mnb);
            suma += sc[j][0] + sc[j][1];
            sumb += sc[j][2] + sc[j][3];
        }
        suma += __shfl_xor_sync(0xffffffffu, suma, 1);
        suma += __shfl_xor_sync(0xffffffffu, suma, 2);
        sumb += __shfl_xor_sync(0xffffffffu, sumb, 1);
        sumb += __shfl_xor_sync(0xffffffffu, sumb, 2);
        lrow[0] = lrow[0] * ala + suma;
        lrow[1] = lrow[1] * alb + sumb;
#pragma unroll
        for (int nb = 0; nb < 16; ++nb) {
            o[nb][0] *= ala; o[nb][1] *= ala;
            o[nb][2] *= alb; o[nb][3] *= alb;
        }

        uint32_t pah[2][4], pal[2][4];
#pragma unroll
        for (int j = 0; j < 2; ++j) {
            split2(sc[2 * j][0],     sc[2 * j][1],     pah[j][0], pal[j][0]);
            split2(sc[2 * j][2],     sc[2 * j][3],     pah[j][1], pal[j][1]);
            split2(sc[2 * j + 1][0], sc[2 * j + 1][1], pah[j][2], pal[j][2]);
            split2(sc[2 * j + 1][2], sc[2 * j + 1][3], pah[j][3], pal[j][3]);
        }

        uint32_t vbase = kvb + 2 * KT_B;
#pragma unroll 1
        for (int j = 0; j < 2; ++j) {
#pragma unroll
            for (int nb2 = 0; nb2 < 8; ++nb2) {
                uint32_t va = vbase + voff + j * 16 * VPADB + nb2 * 32;
                uint32_t h0, h1, h2, h3, l0, l1, l2, l3;
                ldsm4t(h0, h1, h2, h3, va);
                ldsm4t(l0, l1, l2, l3, va + VT_B);
                mma16816(o[2 * nb2],     pah[j][0], pah[j][1], pah[j][2], pah[j][3], h0, h1);
                mma16816(o[2 * nb2],     pah[j][0], pah[j][1], pah[j][2], pah[j][3], l0, l1);
                mma16816(o[2 * nb2],     pal[j][0], pal[j][1], pal[j][2], pal[j][3], h0, h1);
                mma16816(o[2 * nb2 + 1], pah[j][0], pah[j][1], pah[j][2], pah[j][3], h2, h3);
                mma16816(o[2 * nb2 + 1], pah[j][0], pah[j][1], pah[j][2], pah[j][3], l2, l3);
                mma16816(o[2 * nb2 + 1], pal[j][0], pal[j][1], pal[j][2], pal[j][3], h2, h3);
            }
        }
    }

    float inva = 1.0f / lrow[0], invb = 1.0f / lrow[1];
#pragma unroll
    for (int nb = 0; nb < 16; ++nb) {
        int col = h * 128 + nb * 8 + colq;
        uint32_t hA, lA, hB, lB;
        split2(o[nb][0] * inva, o[nb][1] * inva, hA, lA);
        split2(o[nb][2] * invb, o[nb][3] * invb, hB, lB);
        *(uint32_t*)&Oh_g[(long)rowA * 2048 + col] = hA;
        *(uint32_t*)&Ol_g[(long)rowA * 2048 + col] = lA;
        *(uint32_t*)&Oh_g[(long)rowB * 2048 + col] = hB;
        *(uint32_t*)&Ol_g[(long)rowB * 2048 + col] = lB;
    }
}

// ---------------- launch ------------------------------------------------------
extern "C" void kernel_launch(void* const* d_in, const int* in_sizes, int n_in,
                              void* d_out, int out_size)
{
    const float* hidden   = (const float*)d_in[0];
    const int*   pos      = (const int*)d_in[1];
    const float* ln_w     = (const float*)d_in[3];
    const float* wq_a     = (const float*)d_in[4];
    const float* q_a_ln   = (const float*)d_in[5];
    const float* wq_b     = (const float*)d_in[6];
    const float* wkv_a    = (const float*)d_in[7];
    const float* kv_a_ln  = (const float*)d_in[8];
    const float* wkv_b    = (const float*)d_in[9];
    const float* wo       = (const float*)d_in[10];

    float* out   = (float*)d_out;
    float* k_out = out + (long)SEQ * HIDDEN;
    float* v_out = k_out + (long)NHEADS * SEQ * QKD;

    float *p_qackv, *p_q, *p_kv;
    cudaGetSymbolAddress((void**)&p_qackv, g_qackv);
    cudaGetSymbolAddress((void**)&p_q, g_q);
    cudaGetSymbolAddress((void**)&p_kv, g_kv);

    __nv_bfloat16 *h_hi, *h_lo, *qa_hi, *qa_lo, *ckvn_hi, *ckvn_lo, *attn_hi, *attn_lo;
    __nv_bfloat16 *qf_hi, *qf_lo, *k_hi, *k_lo, *v_hi, *v_lo;
    __nv_bfloat16 *wqkva_hi, *wqkva_lo, *wqb_hi, *wqb_lo, *wkvb_hi, *wkvb_lo, *wo_hi, *wo_lo;
    cudaGetSymbolAddress((void**)&h_hi, g_h_hi);       cudaGetSymbolAddress((void**)&h_lo, g_h_lo);
    cudaGetSymbolAddress((void**)&qa_hi, g_qa_hi);     cudaGetSymbolAddress((void**)&qa_lo, g_qa_lo);
    cudaGetSymbolAddress((void**)&ckvn_hi, g_ckvn_hi); cudaGetSymbolAddress((void**)&ckvn_lo, g_ckvn_lo);
    cudaGetSymbolAddress((void**)&attn_hi, g_attn_hi); cudaGetSymbolAddress((void**)&attn_lo, g_attn_lo);
    cudaGetSymbolAddress((void**)&qf_hi, g_qf_hi);     cudaGetSymbolAddress((void**)&qf_lo, g_qf_lo);
    cudaGetSymbolAddress((void**)&k_hi, g_k_hi);       cudaGetSymbolAddress((void**)&k_lo, g_k_lo);
    cudaGetSymbolAddress((void**)&v_hi, g_v_hi);       cudaGetSymbolAddress((void**)&v_lo, g_v_lo);
    cudaGetSymbolAddress((void**)&wqkva_hi, g_wqkva_hi); cudaGetSymbolAddress((void**)&wqkva_lo, g_wqkva_lo);
    cudaGetSymbolAddress((void**)&wqb_hi, g_wqb_hi);   cudaGetSymbolAddress((void**)&wqb_lo, g_wqb_lo);
    cudaGetSymbolAddress((void**)&wkvb_hi, g_wkvb_hi); cudaGetSymbolAddress((void**)&wkvb_lo, g_wkvb_lo);
    cudaGetSymbolAddress((void**)&wo_hi, g_wo_hi);     cudaGetSymbolAddress((void**)&wo_lo, g_wo_lo);

    cudaFuncSetAttribute(gemm_mma, cudaFuncAttributeMaxDynamicSharedMemorySize, GEMM_SMEM);
    cudaFuncSetAttribute(gemm_dual, cudaFuncAttributeMaxDynamicSharedMemorySize, GEMM_SMEM);
    cudaFuncSetAttribute(flash_mma, cudaFuncAttributeMaxDynamicSharedMemorySize, FLASH_SMEM);

    // batched weight conversion (cumulative float4 counts)
    long c0 = (long)QLORA * HIDDEN / 4;               // wq_a
    long c1 = c0 + (long)576 * HIDDEN / 4;            // wkv_a
    long c2 = c1 + (long)3072 * QLORA / 4;            // wq_b
    long c3 = c2 + (long)4096 * KVLORA / 4;           // wkv_b
    long c4 = c3 + (long)HIDDEN * 2048 / 4;           // wo
    cvt_b16_multi<<<1184, 256>>>(
        wq_a,  wqkva_hi, wqkva_lo, c0,
        wkv_a, wqkva_hi + (long)QLORA * HIDDEN, wqkva_lo + (long)QLORA * HIDDEN, c1,
        wq_b,  wqb_hi,  wqb_lo,  c2,
        wkv_b, wkvb_hi, wkvb_lo, c3,
        wo,    wo_hi,   wo_lo,   c4);

    rmsnorm_b16<<<SEQ, 256>>>(hidden, ln_w, h_hi, h_lo, HIDDEN, HIDDEN, HIDDEN);
    gemm_mma<<<dim3(17, SEQ / 128), 256, GEMM_SMEM>>>(
        h_hi, h_lo, HIDDEN, wqkva_hi, wqkva_lo, p_qackv, SEQ, QKVN, HIDDEN, nullptr, 0.f);
    rmsnorm_b16<<<SEQ, 256>>>(p_qackv, q_a_ln, qa_hi, qa_lo, QLORA, QKVN, QLORA);
    rmsnorm_b16<<<SEQ, 256>>>(p_qackv + QLORA, kv_a_ln, ckvn_hi, ckvn_lo, KVLORA, QKVN, KVLORA);
    gemm_dual<<<dim3(24 + 32, SEQ / 128), 256, GEMM_SMEM>>>(
        qa_hi, qa_lo, QLORA, wqb_hi, wqb_lo, p_q, 3072, QLORA,
        ckvn_hi, ckvn_lo, KVLORA, wkvb_hi, wkvb_lo, p_kv, 4096, KVLORA, 24);
    rope_scatter<<<SEQ, 256>>>(p_q, p_qackv, p_kv, pos, qf_hi, qf_lo,
                               k_out, k_hi, k_lo, v_out, v_hi, v_lo);
    flash_mma<<<dim3(SEQ / 128, NHEADS), 256, FLASH_SMEM>>>(
        qf_hi, qf_lo, k_hi, k_lo, v_hi, v_lo, attn_hi, attn_lo);
    gemm_mma<<<dim3(HIDDEN / 128, SEQ / 128), 256, GEMM_SMEM>>>(
        attn_hi, attn_lo, 2048, wo_hi, wo_lo, out, SEQ, HIDDEN, 2048,
        hidden, RESID_SCALE);
}